// round 14
// baseline (speedup 1.0000x reference)
#include <cuda_runtime.h>
#include <cuda_fp16.h>
#include <cstdint>

#define N_ROI 262144
#define DIM   256
#define HID   64
#define NNET  128
#define TILE_M 128
#define NTILE (N_ROI / TILE_M)   // 2048
#define GRID_S 296               // persistent score CTAs (2 per SM)
#define GCAP  4096               // per-group slot capacity (count ~2048 +- 45)
#define POOL_GRID (NNET * 8)

typedef unsigned long long ull;

// ---------------- scratch ----------------
__device__ ull g_pair[NNET * GCAP];   // (w_bits<<32)|row, region per group
__device__ int g_count[NNET];         // per-row alloc cursor == final count; pool resets
__device__ int g_pdone;               // pool done-counter (zero-init, pool resets)

// ---------------- smem layout (byte offsets from 1024-aligned base) --------
#define OFF_B1   0
#define OFF_W2   256
#define OFF_B    1024            // 4 chunks x 8KB fp16 = 32KB (resident)
#define OFF_A    33792           // 2 bufs x 16KB = 32KB
#define SMEM_END 66560
#define DSMEM_BYTES (SMEM_END + 1024)

__device__ __forceinline__ uint32_t smem_u32(const void* p) {
    uint32_t a;
    asm("{ .reg .u64 t; cvta.to.shared.u64 t, %1; cvt.u32.u64 %0, t; }"
        : "=r"(a) : "l"(p));
    return a;
}

#define LDSM4(R, ADDR) asm volatile( \
    "ldmatrix.sync.aligned.m8n8.x4.shared.b16 {%0,%1,%2,%3}, [%4];" \
    : "=r"((R)[0]), "=r"((R)[1]), "=r"((R)[2]), "=r"((R)[3]) : "r"(ADDR))

#define MMA(D, A, B0, B1) asm volatile( \
    "mma.sync.aligned.m16n8k16.row.col.f32.f16.f16.f32 " \
    "{%0,%1,%2,%3}, {%4,%5,%6,%7}, {%8,%9}, {%0,%1,%2,%3};" \
    : "+f"((D)[0]), "+f"((D)[1]), "+f"((D)[2]), "+f"((D)[3]) \
    : "r"((A)[0]), "r"((A)[1]), "r"((A)[2]), "r"((A)[3]), "r"(B0), "r"(B1))

// packed fp32 -> fp16 (8 values -> uint4)
__device__ __forceinline__ void cvt8h(const float4& a, const float4& b, uint4& hi) {
    unsigned h0, h1, h2, h3;
    asm("cvt.rn.f16x2.f32 %0, %1, %2;" : "=r"(h0) : "f"(a.y), "f"(a.x));
    asm("cvt.rn.f16x2.f32 %0, %1, %2;" : "=r"(h1) : "f"(a.w), "f"(a.z));
    asm("cvt.rn.f16x2.f32 %0, %1, %2;" : "=r"(h2) : "f"(b.y), "f"(b.x));
    asm("cvt.rn.f16x2.f32 %0, %1, %2;" : "=r"(h3) : "f"(b.w), "f"(b.z));
    hi = make_uint4(h0, h1, h2, h3);
}

// ---------------- score: persistent fp16 HMMA GEMM, warp-independent tiles -
// w[i] = exp( relu(x[i,:] @ W1 + b1) @ W2 )   (max & b2 cancel in softmax)
// Warp w owns rows [16w,16w+16) end-to-end: LDG -> cvt -> STS -> LDSM -> MMA
// -> exp -> per-row atomic reserve -> pair STG. No block syncs after prologue.
__global__ __launch_bounds__(256, 2) void score_kernel(
    const float* __restrict__ x,  const float* __restrict__ W1,
    const float* __restrict__ b1, const float* __restrict__ W2,
    const int* __restrict__ group)
{
    extern __shared__ char dsm[];
    uint32_t raw = smem_u32(dsm);
    uint32_t sb  = (raw + 1023) & ~1023u;
    char* s = dsm + (sb - raw);

    float* sB1 = (float*)(s + OFF_B1);
    float* sW2 = (float*)(s + OFF_W2);

    const int tid = threadIdx.x;
    const int w   = tid >> 5, l = tid & 31;
    const int wrow = w * 16;                 // this warp's row band within tile
    const float4* __restrict__ x4 = (const float4*)x;

    if (tid < 64) { sB1[tid] = b1[tid]; sW2[tid] = W2[tid]; }

    // ---- stage B from W1 directly, ONCE per CTA ----
    // thread tid owns W1 row k=tid; writes transposed fp16 into
    // B[chunk][j][swz(k)]. Per-j warp writes are 64 contiguous bytes.
    {
        const float4* w4 = (const float4*)(W1 + (size_t)tid * HID);
        const int kk = tid & 63;
        char* cb = s + OFF_B + (tid >> 6) * 8192;
        #pragma unroll
        for (int q4 = 0; q4 < 16; q4++) {
            float4 v = w4[q4];
            int j0 = q4 * 4;
            *(__half*)(cb + (j0 + 0) * 128 + ((kk * 2) ^ (((j0 + 0) & 7) * 16))) = __float2half_rn(v.x);
            *(__half*)(cb + (j0 + 1) * 128 + ((kk * 2) ^ (((j0 + 1) & 7) * 16))) = __float2half_rn(v.y);
            *(__half*)(cb + (j0 + 2) * 128 + ((kk * 2) ^ (((j0 + 2) & 7) * 16))) = __float2half_rn(v.z);
            *(__half*)(cb + (j0 + 3) * 128 + ((kk * 2) ^ (((j0 + 3) & 7) * 16))) = __float2half_rn(v.w);
        }
    }

    // ldmatrix address precompute (warp reads only its own 16-row band)
    const uint32_t xw    = (l & 7) * 16;
    const uint32_t a_row = wrow + ((l >> 3) & 1) * 8 + (l & 7);
    const uint32_t a_off = a_row * 128;
    const uint32_t a_x   = (a_row & 7) * 16;
    const uint32_t a_cb  = (l >> 4) * 16;
    const uint32_t b_rb  = ((l >> 4) * 8 + (l & 7)) * 128;
    const uint32_t b_cb  = ((l >> 3) & 1) * 16;

    float d[8][4];
    #pragma unroll
    for (int i = 0; i < 8; i++)
        #pragma unroll
        for (int j = 0; j < 4; j++) d[i][j] = 0.f;

    // per-warp chunk staging: 16 rows x 16 float4 = 8 float4/lane
    float4 rA[4][2];
    #define LDG_CHUNK(R0, c) do { \
        _Pragma("unroll") for (int it = 0; it < 4; it++) { \
            int f = it * 32 + l, row = f >> 3, kg = f & 7; \
            const float4* p = x4 + ((size_t)((R0) + wrow + row) * 64 + (c) * 16 + kg * 2); \
            rA[it][0] = p[0]; rA[it][1] = p[1]; } \
    } while (0)

    #define STS_CHUNK(buf) do { \
        uint32_t ab = OFF_A + (buf) * 16384; \
        _Pragma("unroll") for (int it = 0; it < 4; it++) { \
            int f = it * 32 + l, row = f >> 3, kg = f & 7; \
            int grow = wrow + row; \
            uint32_t off = grow * 128 + ((kg * 16) ^ ((grow & 7) * 16)); \
            uint4 hi; cvt8h(rA[it][0], rA[it][1], hi); \
            *(uint4*)(s + ab + off) = hi; } \
    } while (0)

    LDG_CHUNK(blockIdx.x * TILE_M, 0);       // prefetch tile 0 chunk 0
    __syncthreads();                         // B + sB1/sW2 ready (ONLY block sync)

    for (int tile = blockIdx.x; tile < NTILE; tile += GRID_S) {
        const int row0 = tile * TILE_M;
        STS_CHUNK(0);
        __syncwarp();

        #pragma unroll
        for (int c = 0; c < 4; c++) {
            if (c < 3) LDG_CHUNK(row0, c + 1);
            else if (tile + GRID_S < NTILE) LDG_CHUNK((tile + GRID_S) * TILE_M, 0);

            const uint32_t Ab = sb + OFF_A + (c & 1) * 16384;
            const uint32_t Bc = sb + OFF_B + c * 8192;

            #pragma unroll
            for (int t = 0; t < 4; t++) {
                const uint32_t tcol = t * 32;
                uint32_t ah[4];
                LDSM4(ah, Ab + a_off + ((tcol + a_cb) ^ a_x));
                #pragma unroll
                for (int q = 0; q < 4; q++) {
                    uint32_t bq[4];
                    LDSM4(bq, Bc + q * 2048 + b_rb + ((tcol + b_cb) ^ xw));
                    MMA(d[2 * q],     ah, bq[0], bq[1]);
                    MMA(d[2 * q + 1], ah, bq[2], bq[3]);
                }
            }
            if (c < 3) { STS_CHUNK((c + 1) & 1); __syncwarp(); }
        }

        // ---- epilogue: w = exp(relu(D + b1) . W2), quad reduce, scatter ----
        float sA = 0.f, sB = 0.f;
        #pragma unroll
        for (int nt = 0; nt < 8; nt++) {
            int j0 = nt * 8 + (l & 3) * 2;
            float b0 = sB1[j0], b1v = sB1[j0 + 1];
            float w0 = sW2[j0], w1v = sW2[j0 + 1];
            sA += fmaxf(d[nt][0] + b0, 0.f) * w0 + fmaxf(d[nt][1] + b1v, 0.f) * w1v;
            sB += fmaxf(d[nt][2] + b0, 0.f) * w0 + fmaxf(d[nt][3] + b1v, 0.f) * w1v;
            d[nt][0] = d[nt][1] = d[nt][2] = d[nt][3] = 0.f;   // re-zero for next tile
        }
        sA += __shfl_xor_sync(0xffffffffu, sA, 1);
        sA += __shfl_xor_sync(0xffffffffu, sA, 2);
        sB += __shfl_xor_sync(0xffffffffu, sB, 1);
        sB += __shfl_xor_sync(0xffffffffu, sB, 2);

        if ((l & 3) == 0) {
            int r1 = row0 + wrow + (l >> 2);
            int r2 = r1 + 8;
            float wA = __expf(sA);               // |score| < ~6: exp overflow-safe
            float wB = __expf(sB);
            int g1 = group[r1];
            int g2 = group[r2];
            int p1 = atomicAdd(&g_count[g1], 1); // per-row reserve: 2048/addr over
            int p2 = atomicAdd(&g_count[g2], 1); // ~45us -> no contention
            g_pair[(g1 << 12) + p1] = ((ull)(unsigned)__float_as_int(wA) << 32) | (unsigned)r1;
            g_pair[(g2 << 12) + p2] = ((ull)(unsigned)__float_as_int(wB) << 32) | (unsigned)r2;
        }
        __syncwarp();   // scatter lanes done before next tile's STS reuses regs
    }
}

// ---------------- weighted pooling (denom in-flight; resets g_count) -------
__global__ __launch_bounds__(256) void pool_kernel(
    const float* __restrict__ x, float* __restrict__ out)
{
    int g     = blockIdx.x >> 3;
    int chunk = blockIdx.x & 7;
    int rs    = threadIdx.x >> 3;
    int ct    = threadIdx.x & 7;
    int start = g << 12;                 // static region base
    int cnt   = g_count[g];
    int cb    = chunk * 8 + ct;
    const float4* __restrict__ x4 = (const float4*)x;

    float4 acc = make_float4(0.f, 0.f, 0.f, 0.f);
    float wsum = 0.f;
    int r = rs;
    for (; r + 96 < cnt; r += 128) {
        ull p0 = g_pair[start + r];
        ull p1 = g_pair[start + r + 32];
        ull p2 = g_pair[start + r + 64];
        ull p3 = g_pair[start + r + 96];
        float w0 = __int_as_float((int)(p0 >> 32));
        float w1 = __int_as_float((int)(p1 >> 32));
        float w2 = __int_as_float((int)(p2 >> 32));
        float w3 = __int_as_float((int)(p3 >> 32));
        if (ct == 0) wsum += (w0 + w1) + (w2 + w3);
        float4 v0 = x4[(size_t)(unsigned)p0 * 64 + cb];
        float4 v1 = x4[(size_t)(unsigned)p1 * 64 + cb];
        float4 v2 = x4[(size_t)(unsigned)p2 * 64 + cb];
        float4 v3 = x4[(size_t)(unsigned)p3 * 64 + cb];
        acc.x += w0 * v0.x; acc.y += w0 * v0.y; acc.z += w0 * v0.z; acc.w += w0 * v0.w;
        acc.x += w1 * v1.x; acc.y += w1 * v1.y; acc.z += w1 * v1.z; acc.w += w1 * v1.w;
        acc.x += w2 * v2.x; acc.y += w2 * v2.y; acc.z += w2 * v2.z; acc.w += w2 * v2.w;
        acc.x += w3 * v3.x; acc.y += w3 * v3.y; acc.z += w3 * v3.z; acc.w += w3 * v3.w;
    }
    for (; r < cnt; r += 32) {
        ull p = g_pair[start + r];
        float w = __int_as_float((int)(p >> 32));
        if (ct == 0) wsum += w;
        float4 v = x4[(size_t)(unsigned)p * 64 + cb];
        acc.x += w * v.x; acc.y += w * v.y; acc.z += w * v.z; acc.w += w * v.w;
    }

    __shared__ float4 red[32][8];
    __shared__ float  wred[32];
    red[rs][ct] = acc;
    if (ct == 0) wred[rs] = wsum;
    __syncthreads();
    #pragma unroll
    for (int o = 16; o >= 1; o >>= 1) {
        if (rs < o) {
            float4 t = red[rs + o][ct];
            float4 u = red[rs][ct];
            u.x += t.x; u.y += t.y; u.z += t.z; u.w += t.w;
            red[rs][ct] = u;
            if (ct == 0) wred[rs] += wred[rs + o];
        }
        __syncthreads();
    }
    if (rs == 0) {
        float den = wred[0];
        float inv = (den > 0.f) ? (1.f / den) : 0.f;
        float4 v = red[0][ct];
        v.x *= inv; v.y *= inv; v.z *= inv; v.w *= inv;
        ((float4*)out)[(size_t)g * 64 + cb] = v;
    }

    // last block resets g_count + done flag for the next (graph-replayed) run;
    // all blocks have already read their cnt before incrementing the counter.
    if (threadIdx.x == 0) {
        __threadfence();
        int t = atomicAdd(&g_pdone, 1);
        if (t == POOL_GRID - 1) {
            int4 z = make_int4(0, 0, 0, 0);
            #pragma unroll
            for (int i = 0; i < NNET / 4; i++) ((int4*)g_count)[i] = z;
            g_pdone = 0;
        }
    }
}

// ---------------- launch ----------------
extern "C" void kernel_launch(void* const* d_in, const int* in_sizes, int n_in,
                              void* d_out, int out_size) {
    const float* x   = (const float*)d_in[0];
    const int*   grp = (const int*)d_in[1];
    const float* W1  = (const float*)d_in[2];
    const float* b1  = (const float*)d_in[3];
    const float* W2  = (const float*)d_in[4];
    // b2 (d_in[5]) cancels under softmax shift-invariance.

    cudaFuncSetAttribute(score_kernel,
        cudaFuncAttributeMaxDynamicSharedMemorySize, DSMEM_BYTES);

    score_kernel<<<GRID_S, 256, DSMEM_BYTES>>>(x, W1, b1, W2, grp);
    pool_kernel<<<POOL_GRID, 256>>>(x, (float*)d_out);
}

// round 15
// speedup vs baseline: 1.4426x; 1.4426x over previous
#include <cuda_runtime.h>
#include <cuda_fp16.h>
#include <cstdint>

#define N_ROI 262144
#define DIM   256
#define HID   64
#define NNET  128
#define TILE_M 128
#define NTILE (N_ROI / TILE_M)   // 2048
#define GRID_S 296               // persistent score CTAs (2 per SM)
#define GCAP  4096               // per-group slot capacity (count ~2048 +- 45)

typedef unsigned long long ull;

// ---------------- scratch ----------------
__device__ ull   g_pair[NNET * GCAP];                // (w_bits<<32)|row, region per group
__device__ __align__(16) __half g_Wt[HID * DIM];     // W1^T fp16 [64][256]
__device__ int   g_count[NNET];                      // doubles as allocation cursor

// ---------------- smem layout (byte offsets from 1024-aligned base) --------
#define OFF_B1   0
#define OFF_W2   256
#define OFF_CNT  512
#define OFF_BASE 1024
#define OFF_RANK 1536
#define OFF_SG   2560            // 512 : group per row
#define OFF_B    4096            // 4 chunks x 8KB fp16 = 32KB (resident)
#define OFF_A    36864           // 2 bufs x 16KB = 32KB
#define SMEM_END 69632
#define DSMEM_BYTES (SMEM_END + 1024)

__device__ __forceinline__ uint32_t smem_u32(const void* p) {
    uint32_t a;
    asm("{ .reg .u64 t; cvta.to.shared.u64 t, %1; cvt.u32.u64 %0, t; }"
        : "=r"(a) : "l"(p));
    return a;
}

#define LDSM4(R, ADDR) asm volatile( \
    "ldmatrix.sync.aligned.m8n8.x4.shared.b16 {%0,%1,%2,%3}, [%4];" \
    : "=r"((R)[0]), "=r"((R)[1]), "=r"((R)[2]), "=r"((R)[3]) : "r"(ADDR))

#define MMA(D, A, B0, B1) asm volatile( \
    "mma.sync.aligned.m16n8k16.row.col.f32.f16.f16.f32 " \
    "{%0,%1,%2,%3}, {%4,%5,%6,%7}, {%8,%9}, {%0,%1,%2,%3};" \
    : "+f"((D)[0]), "+f"((D)[1]), "+f"((D)[2]), "+f"((D)[3]) \
    : "r"((A)[0]), "r"((A)[1]), "r"((A)[2]), "r"((A)[3]), "r"(B0), "r"(B1))

// packed fp32 -> fp16 (8 values -> uint4)
__device__ __forceinline__ void cvt8h(const float4& a, const float4& b, uint4& hi) {
    unsigned h0, h1, h2, h3;
    asm("cvt.rn.f16x2.f32 %0, %1, %2;" : "=r"(h0) : "f"(a.y), "f"(a.x));
    asm("cvt.rn.f16x2.f32 %0, %1, %2;" : "=r"(h1) : "f"(a.w), "f"(a.z));
    asm("cvt.rn.f16x2.f32 %0, %1, %2;" : "=r"(h2) : "f"(b.y), "f"(b.x));
    asm("cvt.rn.f16x2.f32 %0, %1, %2;" : "=r"(h3) : "f"(b.w), "f"(b.z));
    hi = make_uint4(h0, h1, h2, h3);
}

// ---------------- prep: W1^T fp16 + count init ----------------
__global__ void prep_kernel(const float* __restrict__ W1) {
    int t = blockIdx.x * 256 + threadIdx.x;          // 16384 threads
    int j = t >> 8, k = t & 255;
    g_Wt[j * DIM + k] = __float2half_rn(W1[(size_t)k * HID + j]);
    if (t < NNET) g_count[t] = 0;
}

// ---------------- score: persistent fp16 HMMA GEMM + exp + inline scatter --
// w[i] = exp( relu(x[i,:] @ W1 + b1) @ W2 )   (max & b2 cancel in softmax)
// 296 persistent CTAs; B staged once; cross-tile chunk-0 prefetch.
__global__ __launch_bounds__(256, 2) void score_kernel(
    const float* __restrict__ x, const float* __restrict__ b1,
    const float* __restrict__ W2, const int* __restrict__ group)
{
    extern __shared__ char dsm[];
    uint32_t raw = smem_u32(dsm);
    uint32_t sb  = (raw + 1023) & ~1023u;
    char* s = dsm + (sb - raw);

    float* sB1   = (float*)(s + OFF_B1);
    float* sW2   = (float*)(s + OFF_W2);
    int*   sCnt  = (int*)(s + OFF_CNT);
    int*   sBase = (int*)(s + OFF_BASE);
    int*   sRank = (int*)(s + OFF_RANK);
    int*   sgi   = (int*)(s + OFF_SG);

    const int tid = threadIdx.x;
    const int w   = tid >> 5, l = tid & 31;
    const float4* __restrict__ x4 = (const float4*)x;

    if (tid < 64) { sB1[tid] = b1[tid]; sW2[tid] = W2[tid]; }
    if (tid < NNET) sCnt[tid] = 0;

    // ---- stage B (W1^T fp16, all 4 K-chunks) ONCE per CTA, swizzled ----
    #pragma unroll
    for (int it = 0; it < 8; it++) {
        int f = it * 256 + tid;                  // 2048 16B-groups
        int c = f >> 9, rem = f & 511, n = rem >> 3, kg = rem & 7;
        int src = n * DIM + c * 64 + kg * 8;
        uint32_t dst = OFF_B + c * 8192 + n * 128 + ((kg * 16) ^ ((n & 7) * 16));
        *(uint4*)(s + dst) = *(const uint4*)(g_Wt + src);
    }

    // ldmatrix address precompute
    const uint32_t xw    = (l & 7) * 16;
    const uint32_t a_row = w * 16 + ((l >> 3) & 1) * 8 + (l & 7);
    const uint32_t a_off = a_row * 128;
    const uint32_t a_x   = (a_row & 7) * 16;
    const uint32_t a_cb  = (l >> 4) * 16;
    const uint32_t b_rb  = ((l >> 4) * 8 + (l & 7)) * 128;
    const uint32_t b_cb  = ((l >> 3) & 1) * 16;

    float d[8][4];
    #pragma unroll
    for (int i = 0; i < 8; i++)
        #pragma unroll
        for (int j = 0; j < 4; j++) d[i][j] = 0.f;

    float4 rA[4][2];
    #define LDG_CHUNK(R0, c) do { \
        _Pragma("unroll") for (int it = 0; it < 4; it++) { \
            int f = it * 256 + tid, row = f >> 3, kg = f & 7; \
            const float4* p = x4 + ((size_t)((R0) + row) * 64 + (c) * 16 + kg * 2); \
            rA[it][0] = p[0]; rA[it][1] = p[1]; } \
    } while (0)

    #define STS_CHUNK(buf) do { \
        uint32_t ab = OFF_A + (buf) * 16384; \
        _Pragma("unroll") for (int it = 0; it < 4; it++) { \
            int f = it * 256 + tid, row = f >> 3, kg = f & 7; \
            uint32_t off = row * 128 + ((kg * 16) ^ ((row & 7) * 16)); \
            uint4 hi; cvt8h(rA[it][0], rA[it][1], hi); \
            *(uint4*)(s + ab + off) = hi; } \
    } while (0)

    LDG_CHUNK(blockIdx.x * TILE_M, 0);           // prologue prefetch of tile 0

    for (int tile = blockIdx.x; tile < NTILE; tile += GRID_S) {
        const int row0 = tile * TILE_M;
        __syncthreads();     // prev tile done (scatter, A bufs free); prologue: B+sCnt ready
        STS_CHUNK(0);
        if (tid < NNET) sRank[tid] = 0;
        __syncthreads();     // A buf 0 + sRank ready

        // group load + smem histogram, overlapped with chunk-0 compute
        if (tid < TILE_M) {
            int g = group[row0 + tid];
            sgi[tid] = g;
            atomicAdd(&sCnt[g], 1);
        }

        #pragma unroll
        for (int c = 0; c < 4; c++) {
            // reserve at chunk 1 (hist complete after chunk-0-end sync);
            // ATOMG latency hides under remaining chunks
            if (c == 1 && tid < NNET) {
                int cc = sCnt[tid];
                if (cc > 0) sBase[tid] = atomicAdd(&g_count[tid], cc);
            }
            // sCnt no longer needed after the reserve -> re-zero for next tile
            if (c == 2 && tid < NNET) sCnt[tid] = 0;

            if (c < 3) LDG_CHUNK(row0, c + 1);
            else if (tile + GRID_S < NTILE) LDG_CHUNK((tile + GRID_S) * TILE_M, 0);

            const uint32_t Ab = sb + OFF_A + (c & 1) * 16384;
            const uint32_t Bc = sb + OFF_B + c * 8192;

            #pragma unroll
            for (int t = 0; t < 4; t++) {
                const uint32_t tcol = t * 32;
                uint32_t ah[4];
                LDSM4(ah, Ab + a_off + ((tcol + a_cb) ^ a_x));
                #pragma unroll
                for (int q = 0; q < 4; q++) {
                    uint32_t bq[4];
                    LDSM4(bq, Bc + q * 2048 + b_rb + ((tcol + b_cb) ^ xw));
                    MMA(d[2 * q],     ah, bq[0], bq[1]);
                    MMA(d[2 * q + 1], ah, bq[2], bq[3]);
                }
            }
            if (c < 3) STS_CHUNK((c + 1) & 1);    // overlapped with other warps' MMAs
            __syncthreads();
        }

        // ---- epilogue: w = exp(relu(D + b1) . W2), quad reduce, scatter ----
        float sA = 0.f, sB = 0.f;
        #pragma unroll
        for (int nt = 0; nt < 8; nt++) {
            int j0 = nt * 8 + (l & 3) * 2;
            float b0 = sB1[j0], b1v = sB1[j0 + 1];
            float w0 = sW2[j0], w1v = sW2[j0 + 1];
            sA += fmaxf(d[nt][0] + b0, 0.f) * w0 + fmaxf(d[nt][1] + b1v, 0.f) * w1v;
            sB += fmaxf(d[nt][2] + b0, 0.f) * w0 + fmaxf(d[nt][3] + b1v, 0.f) * w1v;
            d[nt][0] = d[nt][1] = d[nt][2] = d[nt][3] = 0.f;   // re-zero for next tile
        }
        sA += __shfl_xor_sync(0xffffffffu, sA, 1);
        sA += __shfl_xor_sync(0xffffffffu, sA, 2);
        sB += __shfl_xor_sync(0xffffffffu, sB, 1);
        sB += __shfl_xor_sync(0xffffffffu, sB, 2);

        if ((l & 3) == 0) {
            int r1 = w * 16 + (l >> 2);
            int r2 = r1 + 8;
            float wA = __expf(sA);               // |score| < ~6: exp overflow-safe
            float wB = __expf(sB);
            int g1 = sgi[r1];
            int g2 = sgi[r2];
            int rk1 = atomicAdd(&sRank[g1], 1);
            int rk2 = atomicAdd(&sRank[g2], 1);
            int pos1 = (g1 << 12) + sBase[g1] + rk1;
            int pos2 = (g2 << 12) + sBase[g2] + rk2;
            g_pair[pos1] = ((ull)(unsigned)__float_as_int(wA) << 32) | (unsigned)(row0 + r1);
            g_pair[pos2] = ((ull)(unsigned)__float_as_int(wB) << 32) | (unsigned)(row0 + r2);
        }
        // tile-top __syncthreads separates this scatter from next tile's smem reuse
    }
}

// ---------------- weighted pooling (denom computed in-flight) --------------
__global__ __launch_bounds__(256) void pool_kernel(
    const float* __restrict__ x, float* __restrict__ out)
{
    int g     = blockIdx.x >> 3;
    int chunk = blockIdx.x & 7;
    int rs    = threadIdx.x >> 3;
    int ct    = threadIdx.x & 7;
    int start = g << 12;                 // static region base
    int cnt   = g_count[g];
    int cb    = chunk * 8 + ct;
    const float4* __restrict__ x4 = (const float4*)x;

    float4 acc = make_float4(0.f, 0.f, 0.f, 0.f);
    float wsum = 0.f;
    int r = rs;
    for (; r + 96 < cnt; r += 128) {
        ull p0 = g_pair[start + r];
        ull p1 = g_pair[start + r + 32];
        ull p2 = g_pair[start + r + 64];
        ull p3 = g_pair[start + r + 96];
        float w0 = __int_as_float((int)(p0 >> 32));
        float w1 = __int_as_float((int)(p1 >> 32));
        float w2 = __int_as_float((int)(p2 >> 32));
        float w3 = __int_as_float((int)(p3 >> 32));
        if (ct == 0) wsum += (w0 + w1) + (w2 + w3);
        float4 v0 = x4[(size_t)(unsigned)p0 * 64 + cb];
        float4 v1 = x4[(size_t)(unsigned)p1 * 64 + cb];
        float4 v2 = x4[(size_t)(unsigned)p2 * 64 + cb];
        float4 v3 = x4[(size_t)(unsigned)p3 * 64 + cb];
        acc.x += w0 * v0.x; acc.y += w0 * v0.y; acc.z += w0 * v0.z; acc.w += w0 * v0.w;
        acc.x += w1 * v1.x; acc.y += w1 * v1.y; acc.z += w1 * v1.z; acc.w += w1 * v1.w;
        acc.x += w2 * v2.x; acc.y += w2 * v2.y; acc.z += w2 * v2.z; acc.w += w2 * v2.w;
        acc.x += w3 * v3.x; acc.y += w3 * v3.y; acc.z += w3 * v3.z; acc.w += w3 * v3.w;
    }
    for (; r < cnt; r += 32) {
        ull p = g_pair[start + r];
        float w = __int_as_float((int)(p >> 32));
        if (ct == 0) wsum += w;
        float4 v = x4[(size_t)(unsigned)p * 64 + cb];
        acc.x += w * v.x; acc.y += w * v.y; acc.z += w * v.z; acc.w += w * v.w;
    }

    __shared__ float4 red[32][8];
    __shared__ float  wred[32];
    red[rs][ct] = acc;
    if (ct == 0) wred[rs] = wsum;
    __syncthreads();
    #pragma unroll
    for (int o = 16; o >= 1; o >>= 1) {
        if (rs < o) {
            float4 t = red[rs + o][ct];
            float4 u = red[rs][ct];
            u.x += t.x; u.y += t.y; u.z += t.z; u.w += t.w;
            red[rs][ct] = u;
            if (ct == 0) wred[rs] += wred[rs + o];
        }
        __syncthreads();
    }
    if (rs == 0) {
        float den = wred[0];
        float inv = (den > 0.f) ? (1.f / den) : 0.f;
        float4 v = red[0][ct];
        v.x *= inv; v.y *= inv; v.z *= inv; v.w *= inv;
        ((float4*)out)[(size_t)g * 64 + cb] = v;
    }
}

// ---------------- launch ----------------
extern "C" void kernel_launch(void* const* d_in, const int* in_sizes, int n_in,
                              void* d_out, int out_size) {
    const float* x   = (const float*)d_in[0];
    const int*   grp = (const int*)d_in[1];
    const float* W1  = (const float*)d_in[2];
    const float* b1  = (const float*)d_in[3];
    const float* W2  = (const float*)d_in[4];
    // b2 (d_in[5]) cancels under softmax shift-invariance.

    cudaFuncSetAttribute(score_kernel,
        cudaFuncAttributeMaxDynamicSharedMemorySize, DSMEM_BYTES);

    prep_kernel<<<64, 256>>>(W1);
    score_kernel<<<GRID_S, 256, DSMEM_BYTES>>>(x, b1, W2, grp);
    pool_kernel<<<NNET * 8, 256>>>(x, (float*)d_out);
}